// round 11
// baseline (speedup 1.0000x reference)
#include <cuda_runtime.h>
#include <cuda_bf16.h>

#define NN 100000
#define NEMAX 3200000
#define H  32
#define SCAN_TILE 1024
#define MAX_PARTS 128

// ---------------- scratch (device globals; no allocation allowed) ----------
// INVARIANT: g_cnt is all-zero at kernel_launch entry. True at module load
// (zero-init); restored by upd_kernel(doHead) at the end of every launch.
__device__ __align__(16) float g_h   [NN * H];
__device__ __align__(16) float g_p   [NN * H];
__device__ __align__(16) float g_q   [NN * H];
__device__ __align__(16) float g_aggH[NN * H];
__device__ int    g_cnt [NN];
__device__ int    g_off [NN + 1];
__device__ int    g_fill[NN];
__device__ int    g_part[MAX_PARTS];
__device__ int    g_partoff[MAX_PARTS];
__device__ int    g_csrc[NEMAX];                 // PRE-SCALED src*H, dst-sorted
__device__ __align__(16) float g_cef[NEMAX * 4]; // edge features, dst-sorted

// cooperative copy global -> shared
__device__ __forceinline__ void stage(float* __restrict__ s,
                                      const float* __restrict__ g, int count) {
    for (int i = threadIdx.x; i < count; i += blockDim.x) s[i] = g[i];
}

// per-block edge-layout probe: int64 pairs have all-zero odd words
__device__ __forceinline__ int probe_is64(const int* __restrict__ ew, int tid) {
    __shared__ int sIs64;
    if (tid < 32) {
        int odd = ew[2 * tid + 1];
        unsigned nz = __ballot_sync(0xffffffffu, odd != 0);
        if (tid == 0) sIs64 = (nz == 0) ? 1 : 0;
    }
    __syncthreads();
    return sIs64;
}

__device__ __forceinline__ void load_edge_vec(const int* __restrict__ ew, int e, int is64,
                                              int& src, int& dst) {
    if (is64) { int4 t = ((const int4*)ew)[e]; src = t.x; dst = t.z; }
    else      { int2 t = ((const int2*)ew)[e]; src = t.x; dst = t.y; }
}

// x[IN] @ W[IN,H] + b, optional relu. i-outer / k-inner with float4 weight
// rows -> LDS.128 (4 weights per shared-memory issue).
template <int IN, bool RELU>
__device__ __forceinline__ void mlp_layer(const float* __restrict__ x,
                                          float* __restrict__ out,
                                          const float* __restrict__ W,
                                          const float* __restrict__ b) {
    float s[H];
    const float4* bv = (const float4*)b;
#pragma unroll
    for (int k4 = 0; k4 < 8; k4++) {
        float4 t = bv[k4];
        s[4 * k4 + 0] = t.x; s[4 * k4 + 1] = t.y; s[4 * k4 + 2] = t.z; s[4 * k4 + 3] = t.w;
    }
#pragma unroll
    for (int i = 0; i < IN; i++) {
        float xi = x[i];
        const float4* Wr = (const float4*)(W + i * H);
#pragma unroll
        for (int k4 = 0; k4 < 8; k4++) {
            float4 w = Wr[k4];
            s[4 * k4 + 0] = fmaf(xi, w.x, s[4 * k4 + 0]);
            s[4 * k4 + 1] = fmaf(xi, w.y, s[4 * k4 + 1]);
            s[4 * k4 + 2] = fmaf(xi, w.z, s[4 * k4 + 2]);
            s[4 * k4 + 3] = fmaf(xi, w.w, s[4 * k4 + 3]);
        }
    }
#pragma unroll
    for (int k = 0; k < H; k++) out[k] = RELU ? fmaxf(s[k], 0.0f) : s[k];
}

// accumulate x[IN] @ W into s[H] (no bias), float4 weight rows
template <int IN>
__device__ __forceinline__ void mlp_acc(const float* __restrict__ x,
                                        float* __restrict__ s,
                                        const float* __restrict__ W) {
#pragma unroll
    for (int i = 0; i < IN; i++) {
        float xi = x[i];
        const float4* Wr = (const float4*)(W + i * H);
#pragma unroll
        for (int k4 = 0; k4 < 8; k4++) {
            float4 w = Wr[k4];
            s[4 * k4 + 0] = fmaf(xi, w.x, s[4 * k4 + 0]);
            s[4 * k4 + 1] = fmaf(xi, w.y, s[4 * k4 + 1]);
            s[4 * k4 + 2] = fmaf(xi, w.z, s[4 * k4 + 2]);
            s[4 * k4 + 3] = fmaf(xi, w.w, s[4 * k4 + 3]);
        }
    }
}

// compute p,q from register h and store (W = 64xH block of msgW1 in shared)
__device__ __forceinline__ void emit_pq(const float* __restrict__ x,
                                        const float* __restrict__ sW, int v) {
    float o[H];
#pragma unroll
    for (int k = 0; k < H; k++) o[k] = 0.0f;
    mlp_acc<H>(x, o, sW);
    float4* pr = (float4*)(g_p + (size_t)v * H);
#pragma unroll
    for (int j = 0; j < 8; j++)
        pr[j] = make_float4(o[4 * j], o[4 * j + 1], o[4 * j + 2], o[4 * j + 3]);
#pragma unroll
    for (int k = 0; k < H; k++) o[k] = 0.0f;
    mlp_acc<H>(x, o, sW + 32 * H);
    float4* qr = (float4*)(g_q + (size_t)v * H);
#pragma unroll
    for (int j = 0; j < 8; j++)
        qr[j] = make_float4(o[4 * j], o[4 * j + 1], o[4 * j + 2], o[4 * j + 3]);
}

// ---------------- kernels ----------------------------------------------------

// Fused: blocks [0, encBlocks) run the encoder MLP (+ round-0 p,q); remaining
// blocks count in-degrees. g_cnt is zero on entry (invariant), so no race.
__global__ void enc_count_kernel(const float* __restrict__ nf,
                                 const float* __restrict__ w1, const float* __restrict__ b1,
                                 const float* __restrict__ w2, const float* __restrict__ b2,
                                 const float* __restrict__ msgW1,
                                 const int* __restrict__ ew,
                                 int n, int ne, int encBlocks) {
    int tid = threadIdx.x;
    if ((int)blockIdx.x >= encBlocks) {
        int is64 = probe_is64(ew, tid);
        int e = (blockIdx.x - encBlocks) * blockDim.x + tid;
        if (e >= ne) return;
        int src, dst;
        load_edge_vec(ew, e, is64, src, dst);
        atomicAdd(&g_cnt[dst], 1);
        return;
    }
    __shared__ float sW1[16 * H], sB1[H], sW2[H * H], sB2[H], sPQ[64 * H];
    stage(sW1, w1, 16 * H);
    stage(sB1, b1, H);
    stage(sW2, w2, H * H);
    stage(sB2, b2, H);
    stage(sPQ, msgW1, 64 * H);   // round 0 W1[0:64]
    __syncthreads();

    int v = blockIdx.x * blockDim.x + tid;
    if (v >= n) return;
    float x[16];
    const float4* nr = (const float4*)(nf + (size_t)v * 16);
#pragma unroll
    for (int j = 0; j < 4; j++) {
        float4 t = nr[j];
        x[4 * j + 0] = t.x; x[4 * j + 1] = t.y; x[4 * j + 2] = t.z; x[4 * j + 3] = t.w;
    }
    float t1[H];
    mlp_layer<16, true>(x, t1, sW1, sB1);
    float t2[H];
    mlp_layer<H, false>(t1, t2, sW2, sB2);
    float4* hr = (float4*)(g_h + (size_t)v * H);
#pragma unroll
    for (int j = 0; j < 8; j++)
        hr[j] = make_float4(t2[4 * j], t2[4 * j + 1], t2[4 * j + 2], t2[4 * j + 3]);
    emit_pq(t2, sPQ, v);
}

// ---- 3-phase parallel exclusive scan of g_cnt -> g_off/g_fill --------------
__global__ void scan_reduce_kernel(int n) {
    __shared__ int sh[256];
    int b = blockIdx.x, t = threadIdx.x;
    int base = b * SCAN_TILE;
    int s = 0;
    for (int i = t; i < SCAN_TILE; i += 256) {
        int idx = base + i;
        if (idx < n) s += g_cnt[idx];
    }
    sh[t] = s;
    __syncthreads();
    for (int o = 128; o > 0; o >>= 1) {
        if (t < o) sh[t] += sh[t + o];
        __syncthreads();
    }
    if (t == 0) g_part[b] = sh[0];
}

__global__ void scan_parts_kernel(int nb, int n) {
    __shared__ int sh[MAX_PARTS];
    int t = threadIdx.x;
    int v = (t < nb) ? g_part[t] : 0;
    sh[t] = v;
    __syncthreads();
    for (int o = 1; o < MAX_PARTS; o <<= 1) {
        int u = (t >= o) ? sh[t - o] : 0;
        __syncthreads();
        sh[t] += u;
        __syncthreads();
    }
    if (t < nb) g_partoff[t] = (t > 0) ? sh[t - 1] : 0;
    if (t == MAX_PARTS - 1) g_off[n] = sh[MAX_PARTS - 1];
}

__global__ void scan_final_kernel(int n) {
    __shared__ int sh[SCAN_TILE];
    int b = blockIdx.x, t = threadIdx.x;
    int idx = b * SCAN_TILE + t;
    int v = (idx < n) ? g_cnt[idx] : 0;
    sh[t] = v;
    __syncthreads();
    for (int o = 1; o < SCAN_TILE; o <<= 1) {
        int u = (t >= o) ? sh[t - o] : 0;
        __syncthreads();
        sh[t] += u;
        __syncthreads();
    }
    if (idx < n) {
        int ex = g_partoff[b] + sh[t] - v;
        g_off[idx] = ex;
        g_fill[idx] = ex;
    }
}

// scatter edges into dst-sorted CSR: PRE-SCALED src*H + permuted edge features
__global__ void scatter_kernel(const int* __restrict__ ew,
                               const float4* __restrict__ ef, int ne) {
    int tid = threadIdx.x;
    int is64 = probe_is64(ew, tid);
    int e = blockIdx.x * blockDim.x + tid;
    if (e >= ne) return;
    int src, dst;
    load_edge_vec(ew, e, is64, src, dst);
    int slot = atomicAdd(&g_fill[dst], 1);
    g_csrc[slot] = src * H;
    ((float4*)g_cef)[slot] = ef[e];
}

// One warp per dst node, channel per lane. Chunked smem staging; full chunks
// take an unrolled dual-accumulator path with no bounds checks.
__global__ void gather_kernel(const float* __restrict__ msgW1,
                              const float* __restrict__ msgB1,
                              int r, int n) {
    __shared__ int    sSrc[8][32];
    __shared__ float4 sEf[8][32];

    int warp = (blockIdx.x * blockDim.x + threadIdx.x) >> 5;
    int w = (threadIdx.x >> 5) & 7;
    int k = threadIdx.x & 31;
    if (warp >= n) return;
    int v = warp;

    const float* Wc = msgW1 + r * 68 * H + 64 * H;
    float w0 = Wc[0 * H + k];
    float w1 = Wc[1 * H + k];
    float w2 = Wc[2 * H + k];
    float w3 = Wc[3 * H + k];
    float base = msgB1[r * H + k] + g_q[(size_t)v * H + k];
    const float* pk = g_p + k;   // pre-scaled csrc indexes rows directly

    int i0 = g_off[v];
    int i1 = g_off[v + 1];
    float acc0 = 0.0f, acc1 = 0.0f;

    for (int cbase = i0; cbase < i1; cbase += 32) {
        int cnt = i1 - cbase;
        if (cnt > 32) cnt = 32;
        int idx = cbase + k;
        if (k < cnt) {
            sSrc[w][k] = g_csrc[idx];
            sEf[w][k]  = ((const float4*)g_cef)[idx];
        }
        __syncwarp();
        if (cnt == 32) {
#pragma unroll
            for (int j = 0; j < 32; j += 2) {
                int s0 = sSrc[w][j];
                int s1 = sSrc[w][j + 1];
                float4 f0 = sEf[w][j];
                float4 f1 = sEf[w][j + 1];
                float pv0 = pk[s0];
                float pv1 = pk[s1];
                float a = pv0 + base;
                a = fmaf(f0.x, w0, a); a = fmaf(f0.y, w1, a);
                a = fmaf(f0.z, w2, a); a = fmaf(f0.w, w3, a);
                acc0 += fmaxf(a, 0.0f);
                float b = pv1 + base;
                b = fmaf(f1.x, w0, b); b = fmaf(f1.y, w1, b);
                b = fmaf(f1.z, w2, b); b = fmaf(f1.w, w3, b);
                acc1 += fmaxf(b, 0.0f);
            }
        } else {
            for (int j = 0; j < cnt; j++) {
                int s0 = sSrc[w][j];
                float4 f0 = sEf[w][j];
                float pv0 = pk[s0];
                float a = pv0 + base;
                a = fmaf(f0.x, w0, a); a = fmaf(f0.y, w1, a);
                a = fmaf(f0.z, w2, a); a = fmaf(f0.w, w3, a);
                acc0 += fmaxf(a, 0.0f);
            }
        }
        __syncwarp();
    }
    g_aggH[(size_t)v * H + k] = acc0 + acc1;
}

// agg = aggH@W2 + cnt*b2 ; h += MLP(concat(h, agg)).
// doPQ: emit p,q for next round. doHead: compute head, write out, zero g_cnt.
__global__ void upd_kernel(const float* __restrict__ msgW2, const float* __restrict__ msgB2,
                           const float* __restrict__ updW1, const float* __restrict__ updB1,
                           const float* __restrict__ updW2, const float* __restrict__ updB2,
                           const float* __restrict__ msgW1next,
                           const float* __restrict__ hw1, const float* __restrict__ hb1,
                           const float* __restrict__ hw2, const float* __restrict__ hb2,
                           float* __restrict__ out,
                           int doPQ, int doHead, int r, int n) {
    __shared__ float sW2[H * H], sB2[H];
    __shared__ float sU1[64 * H], sUB1[H], sU2[H * H], sUB2[H];
    __shared__ float sPQ[64 * H];   // reused for head W1 when doHead
    __shared__ float sHW2[H], sHB1[H], sHB2[1];
    stage(sW2, msgW2 + r * H * H, H * H);
    stage(sB2, msgB2 + r * H, H);
    stage(sU1, updW1 + r * 64 * H, 64 * H);
    stage(sUB1, updB1 + r * H, H);
    stage(sU2, updW2 + r * H * H, H * H);
    stage(sUB2, updB2 + r * H, H);
    if (doPQ) stage(sPQ, msgW1next, 64 * H);
    if (doHead) {
        stage(sPQ, hw1, H * H);
        stage(sHW2, hw2, H);
        stage(sHB1, hb1, H);
        stage(sHB2, hb2, 1);
    }
    __syncthreads();

    int v = blockIdx.x * blockDim.x + threadIdx.x;
    if (v >= n) return;
    float h[H], a[H];
    const float4* hr = (const float4*)(g_h + (size_t)v * H);
    const float4* ar = (const float4*)(g_aggH + (size_t)v * H);
#pragma unroll
    for (int j = 0; j < 8; j++) {
        float4 t = hr[j];
        h[4 * j + 0] = t.x; h[4 * j + 1] = t.y; h[4 * j + 2] = t.z; h[4 * j + 3] = t.w;
        float4 u = ar[j];
        a[4 * j + 0] = u.x; a[4 * j + 1] = u.y; a[4 * j + 2] = u.z; a[4 * j + 3] = u.w;
    }
    float fc = (float)g_cnt[v];
    if (doHead) g_cnt[v] = 0;   // restore invariant for next launch/replay
    float agg[H];
#pragma unroll
    for (int k = 0; k < H; k++) agg[k] = fc * sB2[k];
    mlp_acc<H>(a, agg, sW2);
    float t[H];
#pragma unroll
    for (int k = 0; k < H; k++) t[k] = sUB1[k];
    mlp_acc<H>(h, t, sU1);
    mlp_acc<H>(agg, t, sU1 + 32 * H);
#pragma unroll
    for (int k = 0; k < H; k++) t[k] = fmaxf(t[k], 0.0f);
    float o[H];
#pragma unroll
    for (int k = 0; k < H; k++) o[k] = sUB2[k];
    mlp_acc<H>(t, o, sU2);
#pragma unroll
    for (int k = 0; k < H; k++) o[k] += h[k];
    if (doHead) {
        float hd[H];
#pragma unroll
        for (int k = 0; k < H; k++) hd[k] = sHB1[k];
        mlp_acc<H>(o, hd, sPQ);
        float s2 = sHB2[0];
#pragma unroll
        for (int k = 0; k < H; k++) s2 = fmaf(fmaxf(hd[k], 0.0f), sHW2[k], s2);
        out[v] = s2;
        return;
    }
    float4* hwp = (float4*)(g_h + (size_t)v * H);
#pragma unroll
    for (int j = 0; j < 8; j++)
        hwp[j] = make_float4(o[4 * j], o[4 * j + 1], o[4 * j + 2], o[4 * j + 3]);
    if (doPQ) emit_pq(o, sPQ, v);
}

// ---------------- launch ----------------------------------------------------
extern "C" void kernel_launch(void* const* d_in, const int* in_sizes, int n_in,
                              void* d_out, int out_size) {
    const float*  nf   = (const float*)d_in[0];
    const int*    ew   = (const int*)d_in[1];
    const float4* ef   = (const float4*)d_in[2];
    const float* encW1 = (const float*)d_in[3];
    const float* encB1 = (const float*)d_in[4];
    const float* encW2 = (const float*)d_in[5];
    const float* encB2 = (const float*)d_in[6];
    const float* msgW1 = (const float*)d_in[7];
    const float* msgB1 = (const float*)d_in[8];
    const float* msgW2 = (const float*)d_in[9];
    const float* msgB2 = (const float*)d_in[10];
    const float* updW1 = (const float*)d_in[11];
    const float* updB1 = (const float*)d_in[12];
    const float* updW2 = (const float*)d_in[13];
    const float* updB2 = (const float*)d_in[14];
    const float* headW1 = (const float*)d_in[15];
    const float* headB1 = (const float*)d_in[16];
    const float* headW2 = (const float*)d_in[17];
    const float* headB2 = (const float*)d_in[18];

    int n  = in_sizes[0] / 16;
    int ne = in_sizes[1] / 2;

    const int FB = 256;
    int encBlocks = (n + FB - 1) / FB;
    int cntBlocks = (ne + FB - 1) / FB;
    const int NB = 128;
    int gn = (n + NB - 1) / NB;
    int gw = (n * 32 + 255) / 256;
    int nb = (n + SCAN_TILE - 1) / SCAN_TILE;

    enc_count_kernel<<<encBlocks + cntBlocks, FB>>>(nf, encW1, encB1, encW2, encB2,
                                                    msgW1, ew, n, ne, encBlocks);
    scan_reduce_kernel<<<nb, 256>>>(n);
    scan_parts_kernel<<<1, MAX_PARTS>>>(nb, n);
    scan_final_kernel<<<nb, SCAN_TILE>>>(n);
    scatter_kernel<<<cntBlocks, FB>>>(ew, ef, ne);
    for (int r = 0; r < 2; r++) {
        gather_kernel<<<gw, 256>>>(msgW1, msgB1, r, n);
        upd_kernel<<<gn, NB>>>(msgW2, msgB2, updW1, updB1, updW2, updB2,
                               msgW1 + 68 * H,
                               headW1, headB1, headW2, headB2, (float*)d_out,
                               (r == 0) ? 1 : 0, (r == 1) ? 1 : 0, r, n);
    }
}

// round 12
// speedup vs baseline: 1.0237x; 1.0237x over previous
#include <cuda_runtime.h>
#include <cuda_bf16.h>

#define NN 100000
#define NEMAX 3200000
#define H  32
#define SCAN_TILE 1024
#define MAX_PARTS 128

// ---------------- scratch (device globals; no allocation allowed) ----------
// INVARIANT: g_cnt is all-zero at kernel_launch entry. True at module load
// (zero-init); restored by upd_kernel(doHead) at the end of every launch.
__device__ __align__(16) float g_h   [NN * H];
__device__ __align__(16) float g_p   [NN * H];
__device__ __align__(16) float g_q   [NN * H];
__device__ __align__(16) float g_aggH[NN * H];
__device__ int    g_cnt [NN];
__device__ int    g_off [NN + 1];
__device__ int    g_fill[NN];
__device__ int    g_part[MAX_PARTS];
__device__ int    g_partoff[MAX_PARTS];
__device__ int    g_csrc[NEMAX];                 // PRE-SCALED src*H, dst-sorted
__device__ __align__(16) float g_cef[NEMAX * 4]; // edge features, dst-sorted

// cooperative copy global -> shared
__device__ __forceinline__ void stage(float* __restrict__ s,
                                      const float* __restrict__ g, int count) {
    for (int i = threadIdx.x; i < count; i += blockDim.x) s[i] = g[i];
}

// per-block edge-layout probe: int64 pairs have all-zero odd words
__device__ __forceinline__ int probe_is64(const int* __restrict__ ew, int tid) {
    __shared__ int sIs64;
    if (tid < 32) {
        int odd = ew[2 * tid + 1];
        unsigned nz = __ballot_sync(0xffffffffu, odd != 0);
        if (tid == 0) sIs64 = (nz == 0) ? 1 : 0;
    }
    __syncthreads();
    return sIs64;
}

__device__ __forceinline__ void load_edge_vec(const int* __restrict__ ew, int e, int is64,
                                              int& src, int& dst) {
    if (is64) { int4 t = ((const int4*)ew)[e]; src = t.x; dst = t.z; }
    else      { int2 t = ((const int2*)ew)[e]; src = t.x; dst = t.y; }
}

// x[IN] @ W[IN,H] + b -> out[H], optional relu. Scalar k-outer (measured-good).
template <int IN, bool RELU>
__device__ __forceinline__ void mlp_layer(const float* __restrict__ x,
                                          float* __restrict__ out,
                                          const float* __restrict__ W,
                                          const float* __restrict__ b) {
#pragma unroll
    for (int k = 0; k < H; k++) {
        float s = b[k];
#pragma unroll
        for (int i = 0; i < IN; i++) s = fmaf(x[i], W[i * H + k], s);
        out[k] = RELU ? fmaxf(s, 0.0f) : s;
    }
}

// compute p,q from register h and store (W = 64xH block of msgW1 in shared)
__device__ __forceinline__ void emit_pq(const float* __restrict__ x,
                                        const float* __restrict__ sW, int v) {
    float o[H];
#pragma unroll
    for (int k = 0; k < H; k++) {
        float s = 0.0f;
#pragma unroll
        for (int i = 0; i < H; i++) s = fmaf(x[i], sW[i * H + k], s);
        o[k] = s;
    }
    float4* pr = (float4*)(g_p + (size_t)v * H);
#pragma unroll
    for (int j = 0; j < 8; j++)
        pr[j] = make_float4(o[4 * j], o[4 * j + 1], o[4 * j + 2], o[4 * j + 3]);
#pragma unroll
    for (int k = 0; k < H; k++) {
        float s = 0.0f;
#pragma unroll
        for (int i = 0; i < H; i++) s = fmaf(x[i], sW[(32 + i) * H + k], s);
        o[k] = s;
    }
    float4* qr = (float4*)(g_q + (size_t)v * H);
#pragma unroll
    for (int j = 0; j < 8; j++)
        qr[j] = make_float4(o[4 * j], o[4 * j + 1], o[4 * j + 2], o[4 * j + 3]);
}

// ---------------- kernels ----------------------------------------------------

// Fused: blocks [0, encBlocks) run the encoder MLP (+ round-0 p,q); remaining
// blocks count in-degrees. g_cnt is zero on entry (invariant), so no race.
__global__ void enc_count_kernel(const float* __restrict__ nf,
                                 const float* __restrict__ w1, const float* __restrict__ b1,
                                 const float* __restrict__ w2, const float* __restrict__ b2,
                                 const float* __restrict__ msgW1,
                                 const int* __restrict__ ew,
                                 int n, int ne, int encBlocks) {
    int tid = threadIdx.x;
    if ((int)blockIdx.x >= encBlocks) {
        int is64 = probe_is64(ew, tid);
        int e = (blockIdx.x - encBlocks) * blockDim.x + tid;
        if (e >= ne) return;
        int src, dst;
        load_edge_vec(ew, e, is64, src, dst);
        atomicAdd(&g_cnt[dst], 1);
        return;
    }
    __shared__ float sW1[16 * H], sB1[H], sW2[H * H], sB2[H], sPQ[64 * H];
    stage(sW1, w1, 16 * H);
    stage(sB1, b1, H);
    stage(sW2, w2, H * H);
    stage(sB2, b2, H);
    stage(sPQ, msgW1, 64 * H);   // round 0 W1[0:64]
    __syncthreads();

    int v = blockIdx.x * blockDim.x + tid;
    if (v >= n) return;
    float x[16];
    const float4* nr = (const float4*)(nf + (size_t)v * 16);
#pragma unroll
    for (int j = 0; j < 4; j++) {
        float4 t = nr[j];
        x[4 * j + 0] = t.x; x[4 * j + 1] = t.y; x[4 * j + 2] = t.z; x[4 * j + 3] = t.w;
    }
    float t1[H];
    mlp_layer<16, true>(x, t1, sW1, sB1);
    float t2[H];
    mlp_layer<H, false>(t1, t2, sW2, sB2);
    float4* hr = (float4*)(g_h + (size_t)v * H);
#pragma unroll
    for (int j = 0; j < 8; j++)
        hr[j] = make_float4(t2[4 * j], t2[4 * j + 1], t2[4 * j + 2], t2[4 * j + 3]);
    emit_pq(t2, sPQ, v);
}

// ---- 3-phase parallel exclusive scan of g_cnt -> g_off/g_fill --------------
__global__ void scan_reduce_kernel(int n) {
    __shared__ int sh[256];
    int b = blockIdx.x, t = threadIdx.x;
    int base = b * SCAN_TILE;
    int s = 0;
    for (int i = t; i < SCAN_TILE; i += 256) {
        int idx = base + i;
        if (idx < n) s += g_cnt[idx];
    }
    sh[t] = s;
    __syncthreads();
    for (int o = 128; o > 0; o >>= 1) {
        if (t < o) sh[t] += sh[t + o];
        __syncthreads();
    }
    if (t == 0) g_part[b] = sh[0];
}

__global__ void scan_parts_kernel(int nb, int n) {
    __shared__ int sh[MAX_PARTS];
    int t = threadIdx.x;
    int v = (t < nb) ? g_part[t] : 0;
    sh[t] = v;
    __syncthreads();
    for (int o = 1; o < MAX_PARTS; o <<= 1) {
        int u = (t >= o) ? sh[t - o] : 0;
        __syncthreads();
        sh[t] += u;
        __syncthreads();
    }
    if (t < nb) g_partoff[t] = (t > 0) ? sh[t - 1] : 0;
    if (t == MAX_PARTS - 1) g_off[n] = sh[MAX_PARTS - 1];
}

__global__ void scan_final_kernel(int n) {
    __shared__ int sh[SCAN_TILE];
    int b = blockIdx.x, t = threadIdx.x;
    int idx = b * SCAN_TILE + t;
    int v = (idx < n) ? g_cnt[idx] : 0;
    sh[t] = v;
    __syncthreads();
    for (int o = 1; o < SCAN_TILE; o <<= 1) {
        int u = (t >= o) ? sh[t - o] : 0;
        __syncthreads();
        sh[t] += u;
        __syncthreads();
    }
    if (idx < n) {
        int ex = g_partoff[b] + sh[t] - v;
        g_off[idx] = ex;
        g_fill[idx] = ex;
    }
}

// scatter edges into dst-sorted CSR: PRE-SCALED src*H + permuted edge features
__global__ void scatter_kernel(const int* __restrict__ ew,
                               const float4* __restrict__ ef, int ne) {
    int tid = threadIdx.x;
    int is64 = probe_is64(ew, tid);
    int e = blockIdx.x * blockDim.x + tid;
    if (e >= ne) return;
    int src, dst;
    load_edge_vec(ew, e, is64, src, dst);
    int slot = atomicAdd(&g_fill[dst], 1);
    g_csrc[slot] = src * H;
    ((float4*)g_cef)[slot] = ef[e];
}

// One warp per dst node, channel per lane. Chunked smem staging (R10's
// measured-good loop); inner loop reads staged edges via LDS broadcast.
__global__ void gather_kernel(const float* __restrict__ msgW1,
                              const float* __restrict__ msgB1,
                              int r, int n) {
    __shared__ int    sSrc[8][32];
    __shared__ float4 sEf[8][32];

    int warp = (blockIdx.x * blockDim.x + threadIdx.x) >> 5;
    int w = (threadIdx.x >> 5) & 7;
    int k = threadIdx.x & 31;
    if (warp >= n) return;
    int v = warp;

    const float* Wc = msgW1 + r * 68 * H + 64 * H;
    float w0 = Wc[0 * H + k];
    float w1 = Wc[1 * H + k];
    float w2 = Wc[2 * H + k];
    float w3 = Wc[3 * H + k];
    float base = msgB1[r * H + k] + g_q[(size_t)v * H + k];
    const float* pk = g_p + k;   // pre-scaled csrc indexes rows directly

    int i0 = g_off[v];
    int i1 = g_off[v + 1];
    float acc = 0.0f;

    for (int cbase = i0; cbase < i1; cbase += 32) {
        int cnt = i1 - cbase;
        if (cnt > 32) cnt = 32;
        int idx = cbase + k;
        if (k < cnt) {
            sSrc[w][k] = g_csrc[idx];
            sEf[w][k]  = ((const float4*)g_cef)[idx];
        }
        __syncwarp();
#pragma unroll 4
        for (int j = 0; j < cnt; j++) {
            int s = sSrc[w][j];
            float4 f = sEf[w][j];
            float pv = pk[s];
            float a = pv + base;
            a = fmaf(f.x, w0, a); a = fmaf(f.y, w1, a);
            a = fmaf(f.z, w2, a); a = fmaf(f.w, w3, a);
            acc += fmaxf(a, 0.0f);
        }
        __syncwarp();
    }
    g_aggH[(size_t)v * H + k] = acc;
}

// agg = aggH@W2 + cnt*b2 ; h += MLP(concat(h, agg)).
// doPQ: emit p,q for next round. doHead: compute head, write out, zero g_cnt.
__global__ void upd_kernel(const float* __restrict__ msgW2, const float* __restrict__ msgB2,
                           const float* __restrict__ updW1, const float* __restrict__ updB1,
                           const float* __restrict__ updW2, const float* __restrict__ updB2,
                           const float* __restrict__ msgW1next,
                           const float* __restrict__ hw1, const float* __restrict__ hb1,
                           const float* __restrict__ hw2, const float* __restrict__ hb2,
                           float* __restrict__ out,
                           int doPQ, int doHead, int r, int n) {
    __shared__ float sW2[H * H], sB2[H];
    __shared__ float sU1[64 * H], sUB1[H], sU2[H * H], sUB2[H];
    __shared__ float sPQ[64 * H];   // reused for head W1 when doHead
    __shared__ float sHW2[H], sHB1[H], sHB2[1];
    stage(sW2, msgW2 + r * H * H, H * H);
    stage(sB2, msgB2 + r * H, H);
    stage(sU1, updW1 + r * 64 * H, 64 * H);
    stage(sUB1, updB1 + r * H, H);
    stage(sU2, updW2 + r * H * H, H * H);
    stage(sUB2, updB2 + r * H, H);
    if (doPQ) stage(sPQ, msgW1next, 64 * H);
    if (doHead) {
        stage(sPQ, hw1, H * H);
        stage(sHW2, hw2, H);
        stage(sHB1, hb1, H);
        stage(sHB2, hb2, 1);
    }
    __syncthreads();

    int v = blockIdx.x * blockDim.x + threadIdx.x;
    if (v >= n) return;
    float h[H], a[H];
    const float4* hr = (const float4*)(g_h + (size_t)v * H);
    const float4* ar = (const float4*)(g_aggH + (size_t)v * H);
#pragma unroll
    for (int j = 0; j < 8; j++) {
        float4 t = hr[j];
        h[4 * j + 0] = t.x; h[4 * j + 1] = t.y; h[4 * j + 2] = t.z; h[4 * j + 3] = t.w;
        float4 u = ar[j];
        a[4 * j + 0] = u.x; a[4 * j + 1] = u.y; a[4 * j + 2] = u.z; a[4 * j + 3] = u.w;
    }
    float fc = (float)g_cnt[v];
    if (doHead) g_cnt[v] = 0;   // restore invariant for next launch/replay
    float agg[H];
#pragma unroll
    for (int k = 0; k < H; k++) {
        float s = fc * sB2[k];
#pragma unroll
        for (int i = 0; i < H; i++) s = fmaf(a[i], sW2[i * H + k], s);
        agg[k] = s;
    }
    float t[H];
#pragma unroll
    for (int k = 0; k < H; k++) {
        float s = sUB1[k];
#pragma unroll
        for (int i = 0; i < H; i++) s = fmaf(h[i], sU1[i * H + k], s);
#pragma unroll
        for (int i = 0; i < H; i++) s = fmaf(agg[i], sU1[(32 + i) * H + k], s);
        t[k] = fmaxf(s, 0.0f);
    }
    float o[H];
#pragma unroll
    for (int k = 0; k < H; k++) {
        float s = sUB2[k];
#pragma unroll
        for (int i = 0; i < H; i++) s = fmaf(t[i], sU2[i * H + k], s);
        o[k] = h[k] + s;
    }
    if (doHead) {
        float s2 = sHB2[0];
#pragma unroll
        for (int k = 0; k < H; k++) {
            float s = sHB1[k];
#pragma unroll
            for (int i = 0; i < H; i++) s = fmaf(o[i], sPQ[i * H + k], s);
            s2 = fmaf(fmaxf(s, 0.0f), sHW2[k], s2);
        }
        out[v] = s2;
        return;
    }
    float4* hwp = (float4*)(g_h + (size_t)v * H);
#pragma unroll
    for (int j = 0; j < 8; j++)
        hwp[j] = make_float4(o[4 * j], o[4 * j + 1], o[4 * j + 2], o[4 * j + 3]);
    if (doPQ) emit_pq(o, sPQ, v);
}

// ---------------- launch ----------------------------------------------------
extern "C" void kernel_launch(void* const* d_in, const int* in_sizes, int n_in,
                              void* d_out, int out_size) {
    const float*  nf   = (const float*)d_in[0];
    const int*    ew   = (const int*)d_in[1];
    const float4* ef   = (const float4*)d_in[2];
    const float* encW1 = (const float*)d_in[3];
    const float* encB1 = (const float*)d_in[4];
    const float* encW2 = (const float*)d_in[5];
    const float* encB2 = (const float*)d_in[6];
    const float* msgW1 = (const float*)d_in[7];
    const float* msgB1 = (const float*)d_in[8];
    const float* msgW2 = (const float*)d_in[9];
    const float* msgB2 = (const float*)d_in[10];
    const float* updW1 = (const float*)d_in[11];
    const float* updB1 = (const float*)d_in[12];
    const float* updW2 = (const float*)d_in[13];
    const float* updB2 = (const float*)d_in[14];
    const float* headW1 = (const float*)d_in[15];
    const float* headB1 = (const float*)d_in[16];
    const float* headW2 = (const float*)d_in[17];
    const float* headB2 = (const float*)d_in[18];

    int n  = in_sizes[0] / 16;
    int ne = in_sizes[1] / 2;

    const int FB = 256;
    int encBlocks = (n + FB - 1) / FB;
    int cntBlocks = (ne + FB - 1) / FB;
    const int NB = 128;
    int gn = (n + NB - 1) / NB;
    int gw = (n * 32 + 255) / 256;
    int nb = (n + SCAN_TILE - 1) / SCAN_TILE;

    enc_count_kernel<<<encBlocks + cntBlocks, FB>>>(nf, encW1, encB1, encW2, encB2,
                                                    msgW1, ew, n, ne, encBlocks);
    scan_reduce_kernel<<<nb, 256>>>(n);
    scan_parts_kernel<<<1, MAX_PARTS>>>(nb, n);
    scan_final_kernel<<<nb, SCAN_TILE>>>(n);
    scatter_kernel<<<cntBlocks, FB>>>(ew, ef, ne);
    for (int r = 0; r < 2; r++) {
        gather_kernel<<<gw, 256>>>(msgW1, msgB1, r, n);
        upd_kernel<<<gn, NB>>>(msgW2, msgB2, updW1, updB1, updW2, updB2,
                               msgW1 + 68 * H,
                               headW1, headB1, headW2, headB2, (float*)d_out,
                               (r == 0) ? 1 : 0, (r == 1) ? 1 : 0, r, n);
    }
}

// round 13
// speedup vs baseline: 1.1055x; 1.0799x over previous
#include <cuda_runtime.h>
#include <cuda_bf16.h>

#define NN 100000
#define NEMAX 3200000
#define H  32
#define SCAN_TILE 1024
#define MAX_PARTS 128

// ---------------- scratch (device globals; no allocation allowed) ----------
// INVARIANT: g_cnt is all-zero at kernel_launch entry. True at module load
// (zero-init); restored by upd_kernel(doHead) at the end of every launch.
__device__ __align__(16) float g_h   [NN * H];
__device__ __align__(16) float g_p   [NN * H];
__device__ __align__(16) float g_q   [NN * H];
__device__ __align__(16) float g_aggH[NN * H];
__device__ int    g_cnt [NN];
__device__ int    g_off [NN + 1];
__device__ int    g_fill[NN];
__device__ int    g_part[MAX_PARTS];
__device__ int    g_csrc[NEMAX];                 // PRE-SCALED src*H, dst-sorted
__device__ __align__(16) float g_cef[NEMAX * 4]; // edge features, dst-sorted

// cooperative copy global -> shared
__device__ __forceinline__ void stage(float* __restrict__ s,
                                      const float* __restrict__ g, int count) {
    for (int i = threadIdx.x; i < count; i += blockDim.x) s[i] = g[i];
}

// per-block edge-layout probe: int64 pairs have all-zero odd words
__device__ __forceinline__ int probe_is64(const int* __restrict__ ew, int tid) {
    __shared__ int sIs64;
    if (tid < 32) {
        int odd = ew[2 * tid + 1];
        unsigned nz = __ballot_sync(0xffffffffu, odd != 0);
        if (tid == 0) sIs64 = (nz == 0) ? 1 : 0;
    }
    __syncthreads();
    return sIs64;
}

__device__ __forceinline__ void load_edge_vec(const int* __restrict__ ew, int e, int is64,
                                              int& src, int& dst) {
    if (is64) { int4 t = ((const int4*)ew)[e]; src = t.x; dst = t.z; }
    else      { int2 t = ((const int2*)ew)[e]; src = t.x; dst = t.y; }
}

// x[IN] @ W[IN,H] + b -> out[H], optional relu. Scalar k-outer (measured-good).
template <int IN, bool RELU>
__device__ __forceinline__ void mlp_layer(const float* __restrict__ x,
                                          float* __restrict__ out,
                                          const float* __restrict__ W,
                                          const float* __restrict__ b) {
#pragma unroll
    for (int k = 0; k < H; k++) {
        float s = b[k];
#pragma unroll
        for (int i = 0; i < IN; i++) s = fmaf(x[i], W[i * H + k], s);
        out[k] = RELU ? fmaxf(s, 0.0f) : s;
    }
}

// compute p,q from register h and store (W = 64xH block of msgW1 in shared)
__device__ __forceinline__ void emit_pq(const float* __restrict__ x,
                                        const float* __restrict__ sW, int v) {
    float o[H];
#pragma unroll
    for (int k = 0; k < H; k++) {
        float s = 0.0f;
#pragma unroll
        for (int i = 0; i < H; i++) s = fmaf(x[i], sW[i * H + k], s);
        o[k] = s;
    }
    float4* pr = (float4*)(g_p + (size_t)v * H);
#pragma unroll
    for (int j = 0; j < 8; j++)
        pr[j] = make_float4(o[4 * j], o[4 * j + 1], o[4 * j + 2], o[4 * j + 3]);
#pragma unroll
    for (int k = 0; k < H; k++) {
        float s = 0.0f;
#pragma unroll
        for (int i = 0; i < H; i++) s = fmaf(x[i], sW[(32 + i) * H + k], s);
        o[k] = s;
    }
    float4* qr = (float4*)(g_q + (size_t)v * H);
#pragma unroll
    for (int j = 0; j < 8; j++)
        qr[j] = make_float4(o[4 * j], o[4 * j + 1], o[4 * j + 2], o[4 * j + 3]);
}

// ---------------- kernels ----------------------------------------------------

// per-node in-degree. g_cnt is zero on entry (invariant), so no zeroing pass.
__global__ void count_kernel(const int* __restrict__ ew, int ne) {
    int tid = threadIdx.x;
    int is64 = probe_is64(ew, tid);
    int e = blockIdx.x * blockDim.x + tid;
    if (e >= ne) return;
    int src, dst;
    load_edge_vec(ew, e, is64, src, dst);
    atomicAdd(&g_cnt[dst], 1);
}

// ---- 2-phase parallel exclusive scan of g_cnt -> g_off/g_fill --------------
__global__ void scan_reduce_kernel(int n) {
    __shared__ int sh[256];
    int b = blockIdx.x, t = threadIdx.x;
    int base = b * SCAN_TILE;
    int s = 0;
    for (int i = t; i < SCAN_TILE; i += 256) {
        int idx = base + i;
        if (idx < n) s += g_cnt[idx];
    }
    sh[t] = s;
    __syncthreads();
    for (int o = 128; o > 0; o >>= 1) {
        if (t < o) sh[t] += sh[t + o];
        __syncthreads();
    }
    if (t == 0) g_part[b] = sh[0];
}

// each block serially prefixes the <=98 partials (thread 0), then scans its tile
__global__ void scan_final_kernel(int n, int nb) {
    __shared__ int sh[SCAN_TILE];
    __shared__ int shEx;
    int b = blockIdx.x, t = threadIdx.x;
    int idx = b * SCAN_TILE + t;
    int v = (idx < n) ? g_cnt[idx] : 0;
    sh[t] = v;
    if (t == 0) {
        int ex = 0;
        for (int j = 0; j < b; j++) ex += g_part[j];
        shEx = ex;
    }
    __syncthreads();
    for (int o = 1; o < SCAN_TILE; o <<= 1) {
        int u = (t >= o) ? sh[t - o] : 0;
        __syncthreads();
        sh[t] += u;
        __syncthreads();
    }
    int ex = shEx;
    if (idx < n) {
        int off = ex + sh[t] - v;
        g_off[idx] = off;
        g_fill[idx] = off;
    }
    if (b == nb - 1 && t == SCAN_TILE - 1) g_off[n] = ex + sh[SCAN_TILE - 1];
}

// scatter edges into dst-sorted CSR: PRE-SCALED src*H + permuted edge features
__global__ void scatter_kernel(const int* __restrict__ ew,
                               const float4* __restrict__ ef, int ne) {
    int tid = threadIdx.x;
    int is64 = probe_is64(ew, tid);
    int e = blockIdx.x * blockDim.x + tid;
    if (e >= ne) return;
    int src, dst;
    load_edge_vec(ew, e, is64, src, dst);
    int slot = atomicAdd(&g_fill[dst], 1);
    g_csrc[slot] = src * H;
    ((float4*)g_cef)[slot] = ef[e];
}

// h = MLP(node_features); also round-0 p,q (fused pq).
__global__ void enc_kernel(const float* __restrict__ nf,
                           const float* __restrict__ w1, const float* __restrict__ b1,
                           const float* __restrict__ w2, const float* __restrict__ b2,
                           const float* __restrict__ msgW1,
                           int n) {
    __shared__ float sW1[16 * H], sB1[H], sW2[H * H], sB2[H], sPQ[64 * H];
    stage(sW1, w1, 16 * H);
    stage(sB1, b1, H);
    stage(sW2, w2, H * H);
    stage(sB2, b2, H);
    stage(sPQ, msgW1, 64 * H);   // round 0 W1[0:64]
    __syncthreads();

    int v = blockIdx.x * blockDim.x + threadIdx.x;
    if (v >= n) return;
    float x[16];
    const float4* nr = (const float4*)(nf + (size_t)v * 16);
#pragma unroll
    for (int j = 0; j < 4; j++) {
        float4 t = nr[j];
        x[4 * j + 0] = t.x; x[4 * j + 1] = t.y; x[4 * j + 2] = t.z; x[4 * j + 3] = t.w;
    }
    float t1[H];
    mlp_layer<16, true>(x, t1, sW1, sB1);
    float t2[H];
    mlp_layer<H, false>(t1, t2, sW2, sB2);
    float4* hr = (float4*)(g_h + (size_t)v * H);
#pragma unroll
    for (int j = 0; j < 8; j++)
        hr[j] = make_float4(t2[4 * j], t2[4 * j + 1], t2[4 * j + 2], t2[4 * j + 3]);
    emit_pq(t2, sPQ, v);
}

// One warp per dst node, channel per lane. Chunked smem staging (measured-good).
__global__ void gather_kernel(const float* __restrict__ msgW1,
                              const float* __restrict__ msgB1,
                              int r, int n) {
    __shared__ int    sSrc[8][32];
    __shared__ float4 sEf[8][32];

    int warp = (blockIdx.x * blockDim.x + threadIdx.x) >> 5;
    int w = (threadIdx.x >> 5) & 7;
    int k = threadIdx.x & 31;
    if (warp >= n) return;
    int v = warp;

    const float* Wc = msgW1 + r * 68 * H + 64 * H;
    float w0 = Wc[0 * H + k];
    float w1 = Wc[1 * H + k];
    float w2 = Wc[2 * H + k];
    float w3 = Wc[3 * H + k];
    float base = msgB1[r * H + k] + g_q[(size_t)v * H + k];
    const float* pk = g_p + k;   // pre-scaled csrc indexes rows directly

    int i0 = g_off[v];
    int i1 = g_off[v + 1];
    float acc = 0.0f;

    for (int cbase = i0; cbase < i1; cbase += 32) {
        int cnt = i1 - cbase;
        if (cnt > 32) cnt = 32;
        int idx = cbase + k;
        if (k < cnt) {
            sSrc[w][k] = g_csrc[idx];
            sEf[w][k]  = ((const float4*)g_cef)[idx];
        }
        __syncwarp();
#pragma unroll 4
        for (int j = 0; j < cnt; j++) {
            int s = sSrc[w][j];
            float4 f = sEf[w][j];
            float pv = pk[s];
            float a = pv + base;
            a = fmaf(f.x, w0, a); a = fmaf(f.y, w1, a);
            a = fmaf(f.z, w2, a); a = fmaf(f.w, w3, a);
            acc += fmaxf(a, 0.0f);
        }
        __syncwarp();
    }
    g_aggH[(size_t)v * H + k] = acc;
}

// h += MLP(concat(h, agg)) with the msgW2 stage FOLDED:
//   agg@U1b = aggH@(W2@U1b) + fc*(b2@U1b) = aggH@V + fc*u
// V[32x32] and u[32] are computed cooperatively per block.
// doPQ: emit p,q for next round. doHead: compute head, write out, zero g_cnt.
__global__ void upd_kernel(const float* __restrict__ msgW2, const float* __restrict__ msgB2,
                           const float* __restrict__ updW1, const float* __restrict__ updB1,
                           const float* __restrict__ updW2, const float* __restrict__ updB2,
                           const float* __restrict__ msgW1next,
                           const float* __restrict__ hw1, const float* __restrict__ hb1,
                           const float* __restrict__ hw2, const float* __restrict__ hb2,
                           float* __restrict__ out,
                           int doPQ, int doHead, int r, int n) {
    __shared__ float sW2[H * H], sB2[H];
    __shared__ float sU1[64 * H], sUB1[H], sU2[H * H], sUB2[H];
    __shared__ float sV[H * H], sUvec[H];
    __shared__ float sPQ[64 * H];   // reused for head W1 when doHead
    __shared__ float sHW2[H], sHB1[H], sHB2[1];
    stage(sW2, msgW2 + r * H * H, H * H);
    stage(sB2, msgB2 + r * H, H);
    stage(sU1, updW1 + r * 64 * H, 64 * H);
    stage(sUB1, updB1 + r * H, H);
    stage(sU2, updW2 + r * H * H, H * H);
    stage(sUB2, updB2 + r * H, H);
    if (doPQ) stage(sPQ, msgW1next, 64 * H);
    if (doHead) {
        stage(sPQ, hw1, H * H);
        stage(sHW2, hw2, H);
        stage(sHB1, hb1, H);
        stage(sHB2, hb2, 1);
    }
    __syncthreads();
    // cooperative V = W2 @ U1b  (V[j][k] = sum_i W2[j][i] * U1[(32+i)][k])
    for (int idx = threadIdx.x; idx < H * H; idx += blockDim.x) {
        int j = idx >> 5, k = idx & 31;
        float s = 0.0f;
#pragma unroll
        for (int i = 0; i < H; i++)
            s = fmaf(sW2[j * H + i], sU1[(32 + i) * H + k], s);
        sV[idx] = s;
    }
    // u = b2 @ U1b
    if (threadIdx.x < H) {
        int k = threadIdx.x;
        float s = 0.0f;
#pragma unroll
        for (int i = 0; i < H; i++)
            s = fmaf(sB2[i], sU1[(32 + i) * H + k], s);
        sUvec[k] = s;
    }
    __syncthreads();

    int v = blockIdx.x * blockDim.x + threadIdx.x;
    if (v >= n) return;
    float h[H], a[H];
    const float4* hr = (const float4*)(g_h + (size_t)v * H);
    const float4* ar = (const float4*)(g_aggH + (size_t)v * H);
#pragma unroll
    for (int j = 0; j < 8; j++) {
        float4 t = hr[j];
        h[4 * j + 0] = t.x; h[4 * j + 1] = t.y; h[4 * j + 2] = t.z; h[4 * j + 3] = t.w;
        float4 u = ar[j];
        a[4 * j + 0] = u.x; a[4 * j + 1] = u.y; a[4 * j + 2] = u.z; a[4 * j + 3] = u.w;
    }
    float fc = (float)g_cnt[v];
    if (doHead) g_cnt[v] = 0;   // restore invariant for next launch/replay
    float t[H];
#pragma unroll
    for (int k = 0; k < H; k++) {
        float s = fmaf(fc, sUvec[k], sUB1[k]);
#pragma unroll
        for (int i = 0; i < H; i++) s = fmaf(h[i], sU1[i * H + k], s);
#pragma unroll
        for (int i = 0; i < H; i++) s = fmaf(a[i], sV[i * H + k], s);
        t[k] = fmaxf(s, 0.0f);
    }
    float o[H];
#pragma unroll
    for (int k = 0; k < H; k++) {
        float s = sUB2[k];
#pragma unroll
        for (int i = 0; i < H; i++) s = fmaf(t[i], sU2[i * H + k], s);
        o[k] = h[k] + s;
    }
    if (doHead) {
        float s2 = sHB2[0];
#pragma unroll
        for (int k = 0; k < H; k++) {
            float s = sHB1[k];
#pragma unroll
            for (int i = 0; i < H; i++) s = fmaf(o[i], sPQ[i * H + k], s);
            s2 = fmaf(fmaxf(s, 0.0f), sHW2[k], s2);
        }
        out[v] = s2;
        return;
    }
    float4* hwp = (float4*)(g_h + (size_t)v * H);
#pragma unroll
    for (int j = 0; j < 8; j++)
        hwp[j] = make_float4(o[4 * j], o[4 * j + 1], o[4 * j + 2], o[4 * j + 3]);
    if (doPQ) emit_pq(o, sPQ, v);
}

// ---------------- launch ----------------------------------------------------
extern "C" void kernel_launch(void* const* d_in, const int* in_sizes, int n_in,
                              void* d_out, int out_size) {
    const float*  nf   = (const float*)d_in[0];
    const int*    ew   = (const int*)d_in[1];
    const float4* ef   = (const float4*)d_in[2];
    const float* encW1 = (const float*)d_in[3];
    const float* encB1 = (const float*)d_in[4];
    const float* encW2 = (const float*)d_in[5];
    const float* encB2 = (const float*)d_in[6];
    const float* msgW1 = (const float*)d_in[7];
    const float* msgB1 = (const float*)d_in[8];
    const float* msgW2 = (const float*)d_in[9];
    const float* msgB2 = (const float*)d_in[10];
    const float* updW1 = (const float*)d_in[11];
    const float* updB1 = (const float*)d_in[12];
    const float* updW2 = (const float*)d_in[13];
    const float* updB2 = (const float*)d_in[14];
    const float* headW1 = (const float*)d_in[15];
    const float* headB1 = (const float*)d_in[16];
    const float* headW2 = (const float*)d_in[17];
    const float* headB2 = (const float*)d_in[18];

    int n  = in_sizes[0] / 16;
    int ne = in_sizes[1] / 2;

    const int EB = 256;
    int ge = (ne + EB - 1) / EB;
    const int NB = 128;
    int gn = (n + NB - 1) / NB;
    int gw = (n * 32 + 255) / 256;
    int nb = (n + SCAN_TILE - 1) / SCAN_TILE;

    // order: count(1) scan_reduce(2) scan_final(3) scatter(4) enc(5)
    //        gather(6) upd(7) gather(8) upd(9)   — ncu samples slot 4: scatter
    count_kernel<<<ge, EB>>>(ew, ne);
    scan_reduce_kernel<<<nb, 256>>>(n);
    scan_final_kernel<<<nb, SCAN_TILE>>>(n, nb);
    scatter_kernel<<<ge, EB>>>(ew, ef, ne);
    enc_kernel<<<gn, NB>>>(nf, encW1, encB1, encW2, encB2, msgW1, n);
    for (int r = 0; r < 2; r++) {
        gather_kernel<<<gw, 256>>>(msgW1, msgB1, r, n);
        upd_kernel<<<gn, NB>>>(msgW2, msgB2, updW1, updB1, updW2, updB2,
                               msgW1 + 68 * H,
                               headW1, headB1, headW2, headB2, (float*)d_out,
                               (r == 0) ? 1 : 0, (r == 1) ? 1 : 0, r, n);
    }
}